// round 2
// baseline (speedup 1.0000x reference)
#include <cuda_runtime.h>
#include <math.h>

// ---------------- problem constants ----------------
#define BATCH   8
#define NSITES  1024        // 32*32
#define ZWD     8
#define ZID     32
#define KOBJ    48
#define CFD     32
#define CROPSZ  28
#define FAN     (CFD*CROPSZ*CROPSZ)   // 25088
#define MTOT    (KOBJ*BATCH)          // 384
#define WRAW    128
#define PIX     (WRAW*WRAW)           // 16384
#define SMALLF  (2*CROPSZ*CROPSZ)     // 1568

// ---------------- output offsets (flattened tuple, C-order) ----------------
#define OFF_PROBMAP  0u
#define OFF_AREAMAP  8192u
#define OFF_CFEW     16384u
#define OFF_PFEW     16768u
#define OFF_BXF      17152u
#define OFF_BYF      17536u
#define OFF_BWF      17920u
#define OFF_BHF      18304u
#define OFF_BMASK    18688u
#define OFF_BMNON    6310144u
#define OFF_BIMG     12601600u
#define OFF_ZSF      18893056u
#define OFF_ZKF      18896128u
#define OFF_ZIS      18899200u
#define OFF_ZIK      18911488u

// ---------------- device scratch (no allocation allowed) ----------------
__device__ float g_zs   [NSITES*BATCH*ZWD];
__device__ float g_zkl  [NSITES*BATCH*ZWD];
__device__ float g_bx   [NSITES*BATCH];
__device__ float g_by   [NSITES*BATCH];
__device__ float g_bw   [NSITES*BATCH];
__device__ float g_bh   [NSITES*BATCH];
__device__ float g_call [NSITES*BATCH];
__device__ float g_bxf  [MTOT];
__device__ float g_byf  [MTOT];
__device__ float g_bwf  [MTOT];
__device__ float g_bhf  [MTOT];
__device__ float g_cf   [MTOT];
__device__ float g_crop [MTOT*FAN];        // 9.63M floats
__device__ float g_enc  [MTOT*64];
__device__ float g_smallw[MTOT*SMALLF];
__device__ float g_bigw [MTOT*PIX];        // 6.29M floats

// ---------------- helpers ----------------
__device__ __forceinline__ float sigmoidf_(float x){ return 1.0f/(1.0f+expf(-x)); }
__device__ __forceinline__ float softplusf_(float x){ return fmaxf(x,0.0f) + log1pf(expf(-fabsf(x))); }

// ================= K1: per-site zwhere sample/kl, tmaps, boxes, prob/area =================
__global__ void k1_site(const float* __restrict__ logit,
                        const float* __restrict__ zmu,
                        const float* __restrict__ zstd,
                        const float* __restrict__ zeps,
                        const float* __restrict__ wz,   // (4,8)
                        const float* __restrict__ bz,   // (4,)
                        float* __restrict__ out)
{
    int g = blockIdx.x*blockDim.x + threadIdx.x;
    if (g >= BATCH*NSITES) return;
    int b = g >> 10;
    int n = g & 1023;

    float zs[ZWD];
    #pragma unroll
    for (int z = 0; z < ZWD; z++) {
        int idx = (b*ZWD + z)*NSITES + n;
        float mu = zmu[idx];
        float sd = zstd[idx];
        float s  = mu + sd * zeps[idx];
        float kl = 0.5f*(mu*mu + sd*sd) - logf(sd) - 0.5f;
        zs[z] = s;
        g_zs [(n*BATCH+b)*ZWD + z] = s;
        g_zkl[(n*BATCH+b)*ZWD + z] = kl;
    }

    float t[4];
    #pragma unroll
    for (int c = 0; c < 4; c++) {
        float a = __ldg(&bz[c]);
        #pragma unroll
        for (int z = 0; z < ZWD; z++) a += zs[z]*__ldg(&wz[c*ZWD+z]);
        t[c] = sigmoidf_(a);
    }
    int ix = n >> 5, iy = n & 31;
    float bx = 4.0f*((float)ix + t[0]);
    float by = 4.0f*((float)iy + t[1]);
    float bw = 10.0f + 30.0f*t[2];
    float bh = 10.0f + 30.0f*t[3];
    g_bx[n*BATCH+b] = bx;  g_by[n*BATCH+b] = by;
    g_bw[n*BATCH+b] = bw;  g_bh[n*BATCH+b] = bh;

    out[OFF_AREAMAP + b*NSITES + n] = bw*bh;
    float c0 = logit[b*NSITES + n];
    out[OFF_PROBMAP + b*NSITES + n] = sigmoidf_(c0);
    g_call[n*BATCH+b] = c0;
}

// ================= K2: per-batch top-48 + gathers + enc bias init =================
__global__ void k2_topk(const float* __restrict__ benc, float* __restrict__ out)
{
    __shared__ float sv[NSITES];
    __shared__ float rv[256];
    __shared__ int   ri[256];
    __shared__ int   win[KOBJ];
    int b = blockIdx.x, t = threadIdx.x;

    for (int i = t; i < NSITES; i += 256) sv[i] = g_call[i*BATCH+b];
    __syncthreads();

    for (int kk = 0; kk < KOBJ; kk++) {
        float bv = -1e30f; int bi = 0;
        for (int i = t; i < NSITES; i += 256) {
            float v = sv[i];
            if (v > bv) { bv = v; bi = i; }      // ascending scan -> lowest idx on tie
        }
        rv[t] = bv; ri[t] = bi;
        __syncthreads();
        for (int s = 128; s > 0; s >>= 1) {
            if (t < s) {
                float v2 = rv[t+s]; int i2 = ri[t+s];
                if (v2 > rv[t] || (v2 == rv[t] && i2 < ri[t])) { rv[t] = v2; ri[t] = i2; }
            }
            __syncthreads();
        }
        if (t == 0) { win[kk] = ri[0]; sv[ri[0]] = -1e30f; }
        __syncthreads();
    }

    if (t < KOBJ) {
        int kk = t, n = win[kk];
        int m = kk*BATCH + b;
        float c = g_call[n*BATCH+b];
        out[OFF_CFEW + m] = c;
        out[OFF_PFEW + m] = sigmoidf_(c);
        float bx = g_bx[n*BATCH+b], by = g_by[n*BATCH+b];
        float bw = g_bw[n*BATCH+b], bh = g_bh[n*BATCH+b];
        out[OFF_BXF + m] = bx;  out[OFF_BYF + m] = by;
        out[OFF_BWF + m] = bw;  out[OFF_BHF + m] = bh;
        g_bxf[m] = bx; g_byf[m] = by; g_bwf[m] = bw; g_bhf[m] = bh;
        g_cf[m] = c;
        #pragma unroll
        for (int z = 0; z < ZWD; z++) {
            out[OFF_ZSF + m*ZWD + z] = g_zs [(n*BATCH+b)*ZWD + z];
            out[OFF_ZKF + m*ZWD + z] = g_zkl[(n*BATCH+b)*ZWD + z];
        }
    }
    // init enc accumulators with bias (runs before K4 via stream order)
    for (int j = b*256 + t; j < MTOT*64; j += BATCH*256)
        g_enc[j] = benc[j & 63];
}

// ================= K3: bilinear crop of features -> g_crop =================
__global__ void k3_crop(const float* __restrict__ feat)
{
    int m = blockIdx.x;              // m = kk*8 + b
    int b = m & 7;
    int t = threadIdx.x;
    __shared__ float xs[CROPSZ], ys[CROPSZ];
    if (t < CROPSZ) {
        float u = ((float)t + 0.5f) / (float)CROPSZ;
        xs[t] = g_bxf[m] + (u - 0.5f)*g_bwf[m] - 0.5f;
        ys[t] = g_byf[m] + (u - 0.5f)*g_bhf[m] - 0.5f;
    }
    __syncthreads();
    const float* fb = feat + (size_t)b*CFD*PIX;
    for (int e = t; e < FAN; e += 256) {
        int c = e / 784;
        int r = e - c*784;
        int i = r / 28;
        int j = r - i*28;
        float x = xs[i], y = ys[j];
        float x0f = floorf(x), y0f = floorf(y);
        int x0 = (int)x0f, y0 = (int)y0f;
        float wx1 = x - x0f, wy1 = y - y0f;
        float wx0 = 1.0f - wx1, wy0 = 1.0f - wy1;
        const float* img = fb + c*PIX;
        bool xa = (x0   >= 0 && x0   < WRAW);
        bool xb = (x0+1 >= 0 && x0+1 < WRAW);
        bool ya = (y0   >= 0 && y0   < WRAW);
        bool yb = (y0+1 >= 0 && y0+1 < WRAW);
        float v00 = (xa&&ya) ? img[x0*WRAW + y0]       : 0.0f;
        float v10 = (xb&&ya) ? img[(x0+1)*WRAW + y0]   : 0.0f;
        float v01 = (xa&&yb) ? img[x0*WRAW + y0+1]     : 0.0f;
        float v11 = (xb&&yb) ? img[(x0+1)*WRAW + y0+1] : 0.0f;
        g_crop[(size_t)m*FAN + e] = v00*wx0*wy0 + v10*wx1*wy0 + v01*wx0*wy1 + v11*wx1*wy1;
    }
}

// ================= K4: enc GEMM (384 x 64 x 25088), split-K + atomics =================
#define MT 32
#define NT 64
#define KT 128
#define KCH 4           // chunks per block; 49*4*128 = 25088
__global__ void k4_gemm(const float* __restrict__ wenc)
{
    __shared__ __align__(16) float As[KT*MT];   // [kk][m]
    __shared__ __align__(16) float Bs[KT*NT];   // [kk][n]
    int t = threadIdx.x;
    int mbase = blockIdx.x * MT;
    int kb0   = blockIdx.y * (KCH*KT);
    int m0 = (t >> 4) << 1;      // 0..30, even
    int n0 = (t & 15) << 2;      // 0..60, mult of 4
    float acc[2][4] = {{0,0,0,0},{0,0,0,0}};

    for (int ch = 0; ch < KCH; ch++) {
        int kb = kb0 + ch*KT;
        for (int idx = t; idx < MT*KT; idx += 256) {
            int mm = idx >> 7, kk = idx & 127;
            As[kk*MT + mm] = g_crop[(size_t)(mbase+mm)*FAN + kb + kk];
        }
        for (int idx = t; idx < NT*KT; idx += 256) {
            int d = idx >> 7, kk = idx & 127;
            Bs[kk*NT + d] = wenc[(size_t)d*FAN + kb + kk];
        }
        __syncthreads();
        #pragma unroll 4
        for (int kk = 0; kk < KT; kk++) {
            float2 a = *(const float2*)&As[kk*MT + m0];
            float4 bv = *(const float4*)&Bs[kk*NT + n0];
            acc[0][0] += a.x*bv.x; acc[0][1] += a.x*bv.y;
            acc[0][2] += a.x*bv.z; acc[0][3] += a.x*bv.w;
            acc[1][0] += a.y*bv.x; acc[1][1] += a.y*bv.y;
            acc[1][2] += a.y*bv.z; acc[1][3] += a.y*bv.w;
        }
        __syncthreads();
    }
    #pragma unroll
    for (int mi = 0; mi < 2; mi++)
        #pragma unroll
        for (int ni = 0; ni < 4; ni++)
            atomicAdd(&g_enc[(mbase+m0+mi)*64 + n0+ni], acc[mi][ni]);
}

// ================= K5: zi sample/kl + dec GEMM + small*c_few =================
__global__ void k5_zi_dec(const float* __restrict__ epszi,
                          const float* __restrict__ wdec,   // (1568, 32)
                          const float* __restrict__ bdec,
                          float* __restrict__ out)
{
    int m = blockIdx.x, t = threadIdx.x;
    __shared__ float zsh[ZID];
    if (t < ZID) {
        float mu = g_enc[m*64 + t];
        float sp = g_enc[m*64 + 32 + t];
        float sd = softplusf_(sp) + 1e-4f;
        float s  = mu + sd * epszi[m*ZID + t];
        float kl = 0.5f*(mu*mu + sd*sd) - logf(sd) - 0.5f;
        out[OFF_ZIS + m*ZID + t] = s;
        out[OFF_ZIK + m*ZID + t] = kl;
        zsh[t] = s;
    }
    __syncthreads();
    float cf = g_cf[m];
    for (int f = t; f < SMALLF; f += 256) {
        const float4* wr = (const float4*)(wdec + (size_t)f*ZID);
        float acc = bdec[f];
        #pragma unroll
        for (int q = 0; q < 8; q++) {
            float4 w4 = wr[q];
            acc += w4.x*zsh[q*4+0] + w4.y*zsh[q*4+1]
                 + w4.z*zsh[q*4+2] + w4.w*zsh[q*4+3];
        }
        float r = (f < 784) ? softplusf_(acc) : sigmoidf_(acc);
        g_smallw[m*SMALLF + f] = r * cf;
    }
}

// ================= K6: uncrop -> big_img (out), big_mask_non (out), big_weight (scratch) ====
__global__ void k6_uncrop(float* __restrict__ out)
{
    int m = blockIdx.x, t = threadIdx.x;
    __shared__ float sm[SMALLF];
    __shared__ float xs[WRAW], ys[WRAW];
    for (int i = t; i < SMALLF; i += 256) sm[i] = g_smallw[m*SMALLF + i];
    if (t < WRAW) {
        float bx = g_bxf[m], bw = g_bwf[m];
        float by = g_byf[m], bh = g_bhf[m];
        xs[t] = ((float)t + 0.5f - (bx - 0.5f*bw)) / bw * (float)CROPSZ - 0.5f;
        ys[t] = ((float)t + 0.5f - (by - 0.5f*bh)) / bh * (float)CROPSZ - 0.5f;
    }
    __syncthreads();
    size_t base = (size_t)m * PIX;
    for (int p = t; p < PIX; p += 256) {
        int X = p >> 7, Y = p & 127;
        float x = xs[X], y = ys[Y];
        float w = 0.0f, im = 0.0f;
        if (x > -1.0f && x < (float)CROPSZ && y > -1.0f && y < (float)CROPSZ) {
            float x0f = floorf(x), y0f = floorf(y);
            int x0 = (int)x0f, y0 = (int)y0f;
            float wx1 = x - x0f, wy1 = y - y0f;
            float wx0 = 1.0f - wx1, wy0 = 1.0f - wy1;
            bool xa = (x0   >= 0 && x0   < CROPSZ);
            bool xb = (x0+1 >= 0 && x0+1 < CROPSZ);
            bool ya = (y0   >= 0 && y0   < CROPSZ);
            bool yb = (y0+1 >= 0 && y0+1 < CROPSZ);
            float w00 = wx0*wy0, w10 = wx1*wy0, w01 = wx0*wy1, w11 = wx1*wy1;
            int i00 = x0*CROPSZ + y0;
            #pragma unroll
            for (int ch = 0; ch < 2; ch++) {
                const float* img = sm + ch*784;
                float v00 = (xa&&ya) ? img[i00]          : 0.0f;
                float v10 = (xb&&ya) ? img[i00+CROPSZ]   : 0.0f;
                float v01 = (xa&&yb) ? img[i00+1]        : 0.0f;
                float v11 = (xb&&yb) ? img[i00+CROPSZ+1] : 0.0f;
                float v = v00*w00 + v10*w10 + v01*w01 + v11*w11;
                if (ch == 0) w = v; else im = v;
            }
        }
        g_bigw[base + p] = w;
        out[OFF_BMNON + base + p] = tanhf(w);
        out[OFF_BIMG  + base + p] = im;
    }
}

// ================= K7: sum over k -> big_mask =================
__global__ void k7_mask(float* __restrict__ out)
{
    int g = blockIdx.x*256 + threadIdx.x;   // < 8*16384
    int b = g >> 14, p = g & 16383;
    float v[KOBJ];
    float s = 0.0f;
    #pragma unroll
    for (int kk = 0; kk < KOBJ; kk++) {
        v[kk] = g_bigw[(size_t)(kk*BATCH+b)*PIX + p];
        s += v[kk];
    }
    float ts = tanhf(s);
    float inv = 1.0f / fmaxf(s, 1e-6f);
    #pragma unroll
    for (int kk = 0; kk < KOBJ; kk++)
        out[OFF_BMASK + (size_t)(kk*BATCH+b)*PIX + p] = ts * (v[kk] * inv);
}

// ================= launcher =================
extern "C" void kernel_launch(void* const* d_in, const int* in_sizes, int n_in,
                              void* d_out, int out_size)
{
    const float* logit = (const float*)d_in[0];
    const float* zmu   = (const float*)d_in[1];
    const float* zstd  = (const float*)d_in[2];
    const float* zeps  = (const float*)d_in[3];
    const float* epszi = (const float*)d_in[4];
    const float* feat  = (const float*)d_in[5];
    const float* wz    = (const float*)d_in[6];
    const float* bz    = (const float*)d_in[7];
    const float* wenc  = (const float*)d_in[8];
    const float* benc  = (const float*)d_in[9];
    const float* wdec  = (const float*)d_in[10];
    const float* bdec  = (const float*)d_in[11];
    float* out = (float*)d_out;

    k1_site<<<32, 256>>>(logit, zmu, zstd, zeps, wz, bz, out);
    k2_topk<<<BATCH, 256>>>(benc, out);
    k3_crop<<<MTOT, 256>>>(feat);
    dim3 g4(MTOT/MT, 49);
    k4_gemm<<<g4, 256>>>(wenc);
    k5_zi_dec<<<MTOT, 256>>>(epszi, wdec, bdec, out);
    k6_uncrop<<<MTOT, 256>>>(out);
    k7_mask<<<(BATCH*PIX)/256, 256>>>(out);
}

// round 3
// speedup vs baseline: 1.2920x; 1.2920x over previous
#include <cuda_runtime.h>
#include <math.h>

// ---------------- problem constants ----------------
#define BATCH   8
#define NSITES  1024        // 32*32
#define ZWD     8
#define ZID     32
#define KOBJ    48
#define CFD     32
#define CROPSZ  28
#define FAN     (CFD*CROPSZ*CROPSZ)   // 25088
#define MTOT    (KOBJ*BATCH)          // 384
#define WRAW    128
#define PIX     (WRAW*WRAW)           // 16384
#define SMALLF  (2*CROPSZ*CROPSZ)     // 1568

// ---------------- output offsets (flattened tuple, C-order) ----------------
#define OFF_PROBMAP  0u
#define OFF_AREAMAP  8192u
#define OFF_CFEW     16384u
#define OFF_PFEW     16768u
#define OFF_BXF      17152u
#define OFF_BYF      17536u
#define OFF_BWF      17920u
#define OFF_BHF      18304u
#define OFF_BMASK    18688u
#define OFF_BMNON    6310144u
#define OFF_BIMG     12601600u
#define OFF_ZSF      18893056u
#define OFF_ZKF      18896128u
#define OFF_ZIS      18899200u
#define OFF_ZIK      18911488u

// ---------------- device scratch (no allocation allowed) ----------------
__device__ float g_zs   [NSITES*BATCH*ZWD];
__device__ float g_zkl  [NSITES*BATCH*ZWD];
__device__ float g_bx   [NSITES*BATCH];
__device__ float g_by   [NSITES*BATCH];
__device__ float g_bw   [NSITES*BATCH];
__device__ float g_bh   [NSITES*BATCH];
__device__ float g_call [NSITES*BATCH];
__device__ float g_bxf  [MTOT];
__device__ float g_byf  [MTOT];
__device__ float g_bwf  [MTOT];
__device__ float g_bhf  [MTOT];
__device__ float g_cf   [MTOT];
__device__ float g_crop [MTOT*FAN];        // 9.63M floats
__device__ float g_enc  [MTOT*64];
__device__ float g_smallw[MTOT*SMALLF];
__device__ float g_bigw [MTOT*PIX];        // 6.29M floats

// ---------------- helpers ----------------
__device__ __forceinline__ float sigmoidf_(float x){ return 1.0f/(1.0f+expf(-x)); }
__device__ __forceinline__ float softplusf_(float x){ return fmaxf(x,0.0f) + log1pf(expf(-fabsf(x))); }

// ================= K1: per-site zwhere sample/kl, tmaps, boxes, prob/area =================
__global__ void k1_site(const float* __restrict__ logit,
                        const float* __restrict__ zmu,
                        const float* __restrict__ zstd,
                        const float* __restrict__ zeps,
                        const float* __restrict__ wz,   // (4,8)
                        const float* __restrict__ bz,   // (4,)
                        float* __restrict__ out)
{
    int g = blockIdx.x*blockDim.x + threadIdx.x;
    if (g >= BATCH*NSITES) return;
    int b = g >> 10;
    int n = g & 1023;

    float zs[ZWD];
    #pragma unroll
    for (int z = 0; z < ZWD; z++) {
        int idx = (b*ZWD + z)*NSITES + n;
        float mu = zmu[idx];
        float sd = zstd[idx];
        float s  = mu + sd * zeps[idx];
        float kl = 0.5f*(mu*mu + sd*sd) - logf(sd) - 0.5f;
        zs[z] = s;
        g_zs [(n*BATCH+b)*ZWD + z] = s;
        g_zkl[(n*BATCH+b)*ZWD + z] = kl;
    }

    float t[4];
    #pragma unroll
    for (int c = 0; c < 4; c++) {
        float a = __ldg(&bz[c]);
        #pragma unroll
        for (int z = 0; z < ZWD; z++) a += zs[z]*__ldg(&wz[c*ZWD+z]);
        t[c] = sigmoidf_(a);
    }
    int ix = n >> 5, iy = n & 31;
    float bx = 4.0f*((float)ix + t[0]);
    float by = 4.0f*((float)iy + t[1]);
    float bw = 10.0f + 30.0f*t[2];
    float bh = 10.0f + 30.0f*t[3];
    g_bx[n*BATCH+b] = bx;  g_by[n*BATCH+b] = by;
    g_bw[n*BATCH+b] = bw;  g_bh[n*BATCH+b] = bh;

    out[OFF_AREAMAP + b*NSITES + n] = bw*bh;
    float c0 = logit[b*NSITES + n];
    out[OFF_PROBMAP + b*NSITES + n] = sigmoidf_(c0);
    g_call[n*BATCH+b] = c0;
}

// ================= K2: per-batch top-48 + gathers + enc bias init =================
__global__ void k2_topk(const float* __restrict__ benc, float* __restrict__ out)
{
    __shared__ float sv[NSITES];
    __shared__ float rv[256];
    __shared__ int   ri[256];
    __shared__ int   win[KOBJ];
    int b = blockIdx.x, t = threadIdx.x;

    for (int i = t; i < NSITES; i += 256) sv[i] = g_call[i*BATCH+b];
    __syncthreads();

    for (int kk = 0; kk < KOBJ; kk++) {
        float bv = -1e30f; int bi = 0;
        for (int i = t; i < NSITES; i += 256) {
            float v = sv[i];
            if (v > bv) { bv = v; bi = i; }      // ascending scan -> lowest idx on tie
        }
        rv[t] = bv; ri[t] = bi;
        __syncthreads();
        for (int s = 128; s > 0; s >>= 1) {
            if (t < s) {
                float v2 = rv[t+s]; int i2 = ri[t+s];
                if (v2 > rv[t] || (v2 == rv[t] && i2 < ri[t])) { rv[t] = v2; ri[t] = i2; }
            }
            __syncthreads();
        }
        if (t == 0) { win[kk] = ri[0]; sv[ri[0]] = -1e30f; }
        __syncthreads();
    }

    if (t < KOBJ) {
        int kk = t, n = win[kk];
        int m = kk*BATCH + b;
        float c = g_call[n*BATCH+b];
        out[OFF_CFEW + m] = c;
        out[OFF_PFEW + m] = sigmoidf_(c);
        float bx = g_bx[n*BATCH+b], by = g_by[n*BATCH+b];
        float bw = g_bw[n*BATCH+b], bh = g_bh[n*BATCH+b];
        out[OFF_BXF + m] = bx;  out[OFF_BYF + m] = by;
        out[OFF_BWF + m] = bw;  out[OFF_BHF + m] = bh;
        g_bxf[m] = bx; g_byf[m] = by; g_bwf[m] = bw; g_bhf[m] = bh;
        g_cf[m] = c;
        #pragma unroll
        for (int z = 0; z < ZWD; z++) {
            out[OFF_ZSF + m*ZWD + z] = g_zs [(n*BATCH+b)*ZWD + z];
            out[OFF_ZKF + m*ZWD + z] = g_zkl[(n*BATCH+b)*ZWD + z];
        }
    }
    // init enc accumulators with bias (runs before K4 via stream order)
    for (int j = b*256 + t; j < MTOT*64; j += BATCH*256)
        g_enc[j] = benc[j & 63];
}

// ================= K3: bilinear crop of features -> g_crop =================
__global__ void k3_crop(const float* __restrict__ feat)
{
    int m = blockIdx.x;              // m = kk*8 + b
    int b = m & 7;
    int t = threadIdx.x;
    __shared__ float xs[CROPSZ], ys[CROPSZ];
    if (t < CROPSZ) {
        float u = ((float)t + 0.5f) / (float)CROPSZ;
        xs[t] = g_bxf[m] + (u - 0.5f)*g_bwf[m] - 0.5f;
        ys[t] = g_byf[m] + (u - 0.5f)*g_bhf[m] - 0.5f;
    }
    __syncthreads();
    const float* fb = feat + (size_t)b*CFD*PIX;
    for (int e = t; e < FAN; e += 256) {
        int c = e / 784;
        int r = e - c*784;
        int i = r / 28;
        int j = r - i*28;
        float x = xs[i], y = ys[j];
        float x0f = floorf(x), y0f = floorf(y);
        int x0 = (int)x0f, y0 = (int)y0f;
        float wx1 = x - x0f, wy1 = y - y0f;
        float wx0 = 1.0f - wx1, wy0 = 1.0f - wy1;
        const float* img = fb + c*PIX;
        bool xa = (x0   >= 0 && x0   < WRAW);
        bool xb = (x0+1 >= 0 && x0+1 < WRAW);
        bool ya = (y0   >= 0 && y0   < WRAW);
        bool yb = (y0+1 >= 0 && y0+1 < WRAW);
        float v00 = (xa&&ya) ? img[x0*WRAW + y0]       : 0.0f;
        float v10 = (xb&&ya) ? img[(x0+1)*WRAW + y0]   : 0.0f;
        float v01 = (xa&&yb) ? img[x0*WRAW + y0+1]     : 0.0f;
        float v11 = (xb&&yb) ? img[(x0+1)*WRAW + y0+1] : 0.0f;
        g_crop[(size_t)m*FAN + e] = v00*wx0*wy0 + v10*wx1*wy0 + v01*wx0*wy1 + v11*wx1*wy1;
    }
}

// ================= K4: enc GEMM (384 x 64 x 25088), 128x64 tile, 4x8 frag ==========
// grid (3, 49): blockIdx.x -> M block of 128, blockIdx.y -> K split of 512 (16 x 32)
#define KT4   32
#define KITER 16
#define ASTR  33      // As row stride (floats), conflict-free
#define BSTR  68      // Bs row stride (floats), 16B-aligned
__global__ void __launch_bounds__(256) k4_gemm(const float* __restrict__ wenc)
{
    __shared__ float As[128*ASTR];   // [m][kk] 16.9KB
    __shared__ float Bs[KT4*BSTR];   // [kk][n] 8.7KB
    int t = threadIdx.x;
    int mbase = blockIdx.x * 128;
    int kb0   = blockIdx.y * (KITER*KT4);
    int m0 = (t >> 3) * 4;        // 0..124
    int n0 = (t & 7) * 8;         // 0..56
    float acc[4][8];
    #pragma unroll
    for (int i = 0; i < 4; i++)
        #pragma unroll
        for (int j = 0; j < 8; j++) acc[i][j] = 0.0f;

    int ldm = t >> 3;             // 0..31
    int ldk = (t & 7) * 4;        // 0..28

    for (int it = 0; it < KITER; it++) {
        int kb = kb0 + it*KT4;
        // stage A: 128 m x 32 kk
        #pragma unroll
        for (int p = 0; p < 4; p++) {
            int mm = p*32 + ldm;
            float4 v = *(const float4*)&g_crop[(size_t)(mbase+mm)*FAN + kb + ldk];
            As[mm*ASTR + ldk+0] = v.x;
            As[mm*ASTR + ldk+1] = v.y;
            As[mm*ASTR + ldk+2] = v.z;
            As[mm*ASTR + ldk+3] = v.w;
        }
        // stage B: 64 d x 32 kk (transposed to [kk][d])
        #pragma unroll
        for (int p = 0; p < 2; p++) {
            int d = p*32 + ldm;
            float4 v = *(const float4*)&wenc[(size_t)d*FAN + kb + ldk];
            Bs[(ldk+0)*BSTR + d] = v.x;
            Bs[(ldk+1)*BSTR + d] = v.y;
            Bs[(ldk+2)*BSTR + d] = v.z;
            Bs[(ldk+3)*BSTR + d] = v.w;
        }
        __syncthreads();
        #pragma unroll 8
        for (int kk = 0; kk < KT4; kk++) {
            float a0 = As[(m0+0)*ASTR + kk];
            float a1 = As[(m0+1)*ASTR + kk];
            float a2 = As[(m0+2)*ASTR + kk];
            float a3 = As[(m0+3)*ASTR + kk];
            float4 b0 = *(const float4*)&Bs[kk*BSTR + n0];
            float4 b1 = *(const float4*)&Bs[kk*BSTR + n0 + 4];
            acc[0][0] += a0*b0.x; acc[0][1] += a0*b0.y; acc[0][2] += a0*b0.z; acc[0][3] += a0*b0.w;
            acc[0][4] += a0*b1.x; acc[0][5] += a0*b1.y; acc[0][6] += a0*b1.z; acc[0][7] += a0*b1.w;
            acc[1][0] += a1*b0.x; acc[1][1] += a1*b0.y; acc[1][2] += a1*b0.z; acc[1][3] += a1*b0.w;
            acc[1][4] += a1*b1.x; acc[1][5] += a1*b1.y; acc[1][6] += a1*b1.z; acc[1][7] += a1*b1.w;
            acc[2][0] += a2*b0.x; acc[2][1] += a2*b0.y; acc[2][2] += a2*b0.z; acc[2][3] += a2*b0.w;
            acc[2][4] += a2*b1.x; acc[2][5] += a2*b1.y; acc[2][6] += a2*b1.z; acc[2][7] += a2*b1.w;
            acc[3][0] += a3*b0.x; acc[3][1] += a3*b0.y; acc[3][2] += a3*b0.z; acc[3][3] += a3*b0.w;
            acc[3][4] += a3*b1.x; acc[3][5] += a3*b1.y; acc[3][6] += a3*b1.z; acc[3][7] += a3*b1.w;
        }
        __syncthreads();
    }
    #pragma unroll
    for (int i = 0; i < 4; i++)
        #pragma unroll
        for (int j = 0; j < 8; j++)
            atomicAdd(&g_enc[(mbase+m0+i)*64 + n0+j], acc[i][j]);
}

// ================= K5: zi sample/kl + dec GEMM + small*c_few =================
__global__ void k5_zi_dec(const float* __restrict__ epszi,
                          const float* __restrict__ wdec,   // (1568, 32)
                          const float* __restrict__ bdec,
                          float* __restrict__ out)
{
    int m = blockIdx.x, t = threadIdx.x;
    __shared__ float zsh[ZID];
    if (t < ZID) {
        float mu = g_enc[m*64 + t];
        float sp = g_enc[m*64 + 32 + t];
        float sd = softplusf_(sp) + 1e-4f;
        float s  = mu + sd * epszi[m*ZID + t];
        float kl = 0.5f*(mu*mu + sd*sd) - logf(sd) - 0.5f;
        out[OFF_ZIS + m*ZID + t] = s;
        out[OFF_ZIK + m*ZID + t] = kl;
        zsh[t] = s;
    }
    __syncthreads();
    float cf = g_cf[m];
    for (int f = t; f < SMALLF; f += 256) {
        const float4* wr = (const float4*)(wdec + (size_t)f*ZID);
        float acc = bdec[f];
        #pragma unroll
        for (int q = 0; q < 8; q++) {
            float4 w4 = wr[q];
            acc += w4.x*zsh[q*4+0] + w4.y*zsh[q*4+1]
                 + w4.z*zsh[q*4+2] + w4.w*zsh[q*4+3];
        }
        float r = (f < 784) ? softplusf_(acc) : sigmoidf_(acc);
        g_smallw[m*SMALLF + f] = r * cf;
    }
}

// ================= K6: uncrop -> big_img (out), big_mask_non (out), big_weight (scratch) ====
__global__ void k6_uncrop(float* __restrict__ out)
{
    int m = blockIdx.x, t = threadIdx.x;
    __shared__ float sm[SMALLF];
    __shared__ float xs[WRAW], ys[WRAW];
    for (int i = t; i < SMALLF; i += 256) sm[i] = g_smallw[m*SMALLF + i];
    if (t < WRAW) {
        float bx = g_bxf[m], bw = g_bwf[m];
        float by = g_byf[m], bh = g_bhf[m];
        xs[t] = ((float)t + 0.5f - (bx - 0.5f*bw)) / bw * (float)CROPSZ - 0.5f;
        ys[t] = ((float)t + 0.5f - (by - 0.5f*bh)) / bh * (float)CROPSZ - 0.5f;
    }
    __syncthreads();
    size_t base = (size_t)m * PIX;
    for (int p = t; p < PIX; p += 256) {
        int X = p >> 7, Y = p & 127;
        float x = xs[X], y = ys[Y];
        float w = 0.0f, im = 0.0f;
        if (x > -1.0f && x < (float)CROPSZ && y > -1.0f && y < (float)CROPSZ) {
            float x0f = floorf(x), y0f = floorf(y);
            int x0 = (int)x0f, y0 = (int)y0f;
            float wx1 = x - x0f, wy1 = y - y0f;
            float wx0 = 1.0f - wx1, wy0 = 1.0f - wy1;
            bool xa = (x0   >= 0 && x0   < CROPSZ);
            bool xb = (x0+1 >= 0 && x0+1 < CROPSZ);
            bool ya = (y0   >= 0 && y0   < CROPSZ);
            bool yb = (y0+1 >= 0 && y0+1 < CROPSZ);
            float w00 = wx0*wy0, w10 = wx1*wy0, w01 = wx0*wy1, w11 = wx1*wy1;
            int i00 = x0*CROPSZ + y0;
            #pragma unroll
            for (int ch = 0; ch < 2; ch++) {
                const float* img = sm + ch*784;
                float v00 = (xa&&ya) ? img[i00]          : 0.0f;
                float v10 = (xb&&ya) ? img[i00+CROPSZ]   : 0.0f;
                float v01 = (xa&&yb) ? img[i00+1]        : 0.0f;
                float v11 = (xb&&yb) ? img[i00+CROPSZ+1] : 0.0f;
                float v = v00*w00 + v10*w10 + v01*w01 + v11*w11;
                if (ch == 0) w = v; else im = v;
            }
        }
        g_bigw[base + p] = w;
        out[OFF_BMNON + base + p] = tanhf(w);
        out[OFF_BIMG  + base + p] = im;
    }
}

// ================= K7: sum over k -> big_mask =================
__global__ void k7_mask(float* __restrict__ out)
{
    int g = blockIdx.x*256 + threadIdx.x;   // < 8*16384
    int b = g >> 14, p = g & 16383;
    float v[KOBJ];
    float s = 0.0f;
    #pragma unroll
    for (int kk = 0; kk < KOBJ; kk++) {
        v[kk] = g_bigw[(size_t)(kk*BATCH+b)*PIX + p];
        s += v[kk];
    }
    float ts = tanhf(s);
    float inv = 1.0f / fmaxf(s, 1e-6f);
    #pragma unroll
    for (int kk = 0; kk < KOBJ; kk++)
        out[OFF_BMASK + (size_t)(kk*BATCH+b)*PIX + p] = ts * (v[kk] * inv);
}

// ================= launcher =================
extern "C" void kernel_launch(void* const* d_in, const int* in_sizes, int n_in,
                              void* d_out, int out_size)
{
    const float* logit = (const float*)d_in[0];
    const float* zmu   = (const float*)d_in[1];
    const float* zstd  = (const float*)d_in[2];
    const float* zeps  = (const float*)d_in[3];
    const float* epszi = (const float*)d_in[4];
    const float* feat  = (const float*)d_in[5];
    const float* wz    = (const float*)d_in[6];
    const float* bz    = (const float*)d_in[7];
    const float* wenc  = (const float*)d_in[8];
    const float* benc  = (const float*)d_in[9];
    const float* wdec  = (const float*)d_in[10];
    const float* bdec  = (const float*)d_in[11];
    float* out = (float*)d_out;

    k1_site<<<32, 256>>>(logit, zmu, zstd, zeps, wz, bz, out);
    k2_topk<<<BATCH, 256>>>(benc, out);
    k3_crop<<<MTOT, 256>>>(feat);
    dim3 g4(3, 49);
    k4_gemm<<<g4, 256>>>(wenc);
    k5_zi_dec<<<MTOT, 256>>>(epszi, wdec, bdec, out);
    k6_uncrop<<<MTOT, 256>>>(out);
    k7_mask<<<(BATCH*PIX)/256, 256>>>(out);
}

// round 4
// speedup vs baseline: 1.6240x; 1.2569x over previous
#include <cuda_runtime.h>
#include <math.h>

// ---------------- problem constants ----------------
#define BATCH   8
#define NSITES  1024        // 32*32
#define ZWD     8
#define ZID     32
#define KOBJ    48
#define CFD     32
#define CROPSZ  28
#define FAN     (CFD*CROPSZ*CROPSZ)   // 25088
#define MTOT    (KOBJ*BATCH)          // 384
#define WRAW    128
#define PIX     (WRAW*WRAW)           // 16384
#define SMALLF  (2*CROPSZ*CROPSZ)     // 1568
#define NSPLIT  98                    // K splits in k4

// ---------------- output offsets (flattened tuple, C-order) ----------------
#define OFF_PROBMAP  0u
#define OFF_AREAMAP  8192u
#define OFF_CFEW     16384u
#define OFF_PFEW     16768u
#define OFF_BXF      17152u
#define OFF_BYF      17536u
#define OFF_BWF      17920u
#define OFF_BHF      18304u
#define OFF_BMASK    18688u
#define OFF_BMNON    6310144u
#define OFF_BIMG     12601600u
#define OFF_ZSF      18893056u
#define OFF_ZKF      18896128u
#define OFF_ZIS      18899200u
#define OFF_ZIK      18911488u

// ---------------- device scratch (no allocation allowed) ----------------
__device__ float g_zs   [NSITES*BATCH*ZWD];
__device__ float g_zkl  [NSITES*BATCH*ZWD];
__device__ float g_bx   [NSITES*BATCH];
__device__ float g_by   [NSITES*BATCH];
__device__ float g_bw   [NSITES*BATCH];
__device__ float g_bh   [NSITES*BATCH];
__device__ float g_call [NSITES*BATCH];
__device__ float g_bxf  [MTOT];
__device__ float g_byf  [MTOT];
__device__ float g_bwf  [MTOT];
__device__ float g_bhf  [MTOT];
__device__ float g_cf   [MTOT];
__device__ float g_crop [MTOT*FAN];          // 9.63M floats
__device__ float g_encp [NSPLIT*MTOT*64];    // 2.41M floats (GEMM partials)
__device__ float g_smallw[MTOT*SMALLF];
__device__ float g_bigw [MTOT*PIX];          // 6.29M floats

// ---------------- helpers ----------------
__device__ __forceinline__ float sigmoidf_(float x){ return 1.0f/(1.0f+expf(-x)); }
__device__ __forceinline__ float softplusf_(float x){ return fmaxf(x,0.0f) + log1pf(expf(-fabsf(x))); }

// ================= K1: per-site zwhere sample/kl, tmaps, boxes, prob/area =================
__global__ void k1_site(const float* __restrict__ logit,
                        const float* __restrict__ zmu,
                        const float* __restrict__ zstd,
                        const float* __restrict__ zeps,
                        const float* __restrict__ wz,   // (4,8)
                        const float* __restrict__ bz,   // (4,)
                        float* __restrict__ out)
{
    int g = blockIdx.x*blockDim.x + threadIdx.x;
    if (g >= BATCH*NSITES) return;
    int b = g >> 10;
    int n = g & 1023;

    float zs[ZWD];
    #pragma unroll
    for (int z = 0; z < ZWD; z++) {
        int idx = (b*ZWD + z)*NSITES + n;
        float mu = zmu[idx];
        float sd = zstd[idx];
        float s  = mu + sd * zeps[idx];
        float kl = 0.5f*(mu*mu + sd*sd) - logf(sd) - 0.5f;
        zs[z] = s;
        g_zs [(n*BATCH+b)*ZWD + z] = s;
        g_zkl[(n*BATCH+b)*ZWD + z] = kl;
    }

    float t[4];
    #pragma unroll
    for (int c = 0; c < 4; c++) {
        float a = __ldg(&bz[c]);
        #pragma unroll
        for (int z = 0; z < ZWD; z++) a += zs[z]*__ldg(&wz[c*ZWD+z]);
        t[c] = sigmoidf_(a);
    }
    int ix = n >> 5, iy = n & 31;
    float bx = 4.0f*((float)ix + t[0]);
    float by = 4.0f*((float)iy + t[1]);
    float bw = 10.0f + 30.0f*t[2];
    float bh = 10.0f + 30.0f*t[3];
    g_bx[n*BATCH+b] = bx;  g_by[n*BATCH+b] = by;
    g_bw[n*BATCH+b] = bw;  g_bh[n*BATCH+b] = bh;

    out[OFF_AREAMAP + b*NSITES + n] = bw*bh;
    float c0 = logit[b*NSITES + n];
    out[OFF_PROBMAP + b*NSITES + n] = sigmoidf_(c0);
    g_call[n*BATCH+b] = c0;
}

// ================= K2: per-batch top-48 (shuffle) + gathers =================
__global__ void __launch_bounds__(1024) k2_topk(float* __restrict__ out)
{
    int b = blockIdx.x, t = threadIdx.x;
    int lane = t & 31, wid = t >> 5;
    __shared__ float wv[32];
    __shared__ int   wi[32];
    __shared__ int   win[KOBJ];

    float v = g_call[t*BATCH + b];   // site value owned by this thread

    for (int kk = 0; kk < KOBJ; kk++) {
        float bv = v; int bi = t;
        #pragma unroll
        for (int o = 16; o > 0; o >>= 1) {
            float ov = __shfl_down_sync(0xffffffffu, bv, o);
            int   oi = __shfl_down_sync(0xffffffffu, bi, o);
            if (ov > bv || (ov == bv && oi < bi)) { bv = ov; bi = oi; }
        }
        if (lane == 0) { wv[wid] = bv; wi[wid] = bi; }
        __syncthreads();
        if (wid == 0) {
            bv = wv[lane]; bi = wi[lane];
            #pragma unroll
            for (int o = 16; o > 0; o >>= 1) {
                float ov = __shfl_down_sync(0xffffffffu, bv, o);
                int   oi = __shfl_down_sync(0xffffffffu, bi, o);
                if (ov > bv || (ov == bv && oi < bi)) { bv = ov; bi = oi; }
            }
            if (lane == 0) win[kk] = bi;
        }
        __syncthreads();
        if (t == win[kk]) v = -1e30f;
    }

    if (t < KOBJ) {
        int kk = t, n = win[kk];
        int m = kk*BATCH + b;
        float c = g_call[n*BATCH+b];
        out[OFF_CFEW + m] = c;
        out[OFF_PFEW + m] = sigmoidf_(c);
        float bx = g_bx[n*BATCH+b], by = g_by[n*BATCH+b];
        float bw = g_bw[n*BATCH+b], bh = g_bh[n*BATCH+b];
        out[OFF_BXF + m] = bx;  out[OFF_BYF + m] = by;
        out[OFF_BWF + m] = bw;  out[OFF_BHF + m] = bh;
        g_bxf[m] = bx; g_byf[m] = by; g_bwf[m] = bw; g_bhf[m] = bh;
        g_cf[m] = c;
        #pragma unroll
        for (int z = 0; z < ZWD; z++) {
            out[OFF_ZSF + m*ZWD + z] = g_zs [(n*BATCH+b)*ZWD + z];
            out[OFF_ZKF + m*ZWD + z] = g_zkl[(n*BATCH+b)*ZWD + z];
        }
    }
}

// ================= K3: bilinear crop of features -> g_crop =================
__global__ void k3_crop(const float* __restrict__ feat)
{
    int m = blockIdx.x;              // m = kk*8 + b
    int b = m & 7;
    int t = threadIdx.x;
    __shared__ float xs[CROPSZ], ys[CROPSZ];
    if (t < CROPSZ) {
        float u = ((float)t + 0.5f) / (float)CROPSZ;
        xs[t] = g_bxf[m] + (u - 0.5f)*g_bwf[m] - 0.5f;
        ys[t] = g_byf[m] + (u - 0.5f)*g_bhf[m] - 0.5f;
    }
    __syncthreads();
    const float* fb = feat + (size_t)b*CFD*PIX;
    for (int e = t; e < FAN; e += 256) {
        int c = e / 784;
        int r = e - c*784;
        int i = r / 28;
        int j = r - i*28;
        float x = xs[i], y = ys[j];
        float x0f = floorf(x), y0f = floorf(y);
        int x0 = (int)x0f, y0 = (int)y0f;
        float wx1 = x - x0f, wy1 = y - y0f;
        float wx0 = 1.0f - wx1, wy0 = 1.0f - wy1;
        const float* img = fb + c*PIX;
        bool xa = (x0   >= 0 && x0   < WRAW);
        bool xb = (x0+1 >= 0 && x0+1 < WRAW);
        bool ya = (y0   >= 0 && y0   < WRAW);
        bool yb = (y0+1 >= 0 && y0+1 < WRAW);
        float v00 = (xa&&ya) ? img[x0*WRAW + y0]       : 0.0f;
        float v10 = (xb&&ya) ? img[(x0+1)*WRAW + y0]   : 0.0f;
        float v01 = (xa&&yb) ? img[x0*WRAW + y0+1]     : 0.0f;
        float v11 = (xb&&yb) ? img[(x0+1)*WRAW + y0+1] : 0.0f;
        g_crop[(size_t)m*FAN + e] = v00*wx0*wy0 + v10*wx1*wy0 + v01*wx0*wy1 + v11*wx1*wy1;
    }
}

// ================= K4: enc GEMM (384 x 64 x 25088), reg-prefetch pipeline ==========
// grid (3, 98): blockIdx.x -> M block of 128, blockIdx.y -> K split of 256 (8 x 32)
#define KT4   32
#define KITER 8
#define ASTR  33
__global__ void __launch_bounds__(256,2) k4_gemm(const float* __restrict__ wenc)
{
    __shared__ float As[128*ASTR];   // [m][kk] 16.9KB
    __shared__ float Bs[KT4*64];     // [kk][n] 8KB
    int t = threadIdx.x;
    int mbase = blockIdx.x * 128;
    int kb0   = blockIdx.y * (KITER*KT4);
    int m0 = (t >> 3) * 4;        // 0..124
    int n0 = (t & 7) * 8;         // 0..56
    int ldm = t >> 3;             // 0..31
    int ldk = (t & 7) * 4;        // 0,4,..28
    int dB  = t & 63;             // 0..63
    int kqB = (t >> 6) * 8;       // 0,8,16,24

    float acc[4][8];
    #pragma unroll
    for (int i = 0; i < 4; i++)
        #pragma unroll
        for (int j = 0; j < 8; j++) acc[i][j] = 0.0f;

    float4 ra[4], rb0, rb1;
    // prefetch iter 0
    #pragma unroll
    for (int p = 0; p < 4; p++)
        ra[p] = *(const float4*)&g_crop[(size_t)(mbase + p*32 + ldm)*FAN + kb0 + ldk];
    rb0 = *(const float4*)&wenc[(size_t)dB*FAN + kb0 + kqB];
    rb1 = *(const float4*)&wenc[(size_t)dB*FAN + kb0 + kqB + 4];

    for (int it = 0; it < KITER; it++) {
        // commit staged regs to smem
        #pragma unroll
        for (int p = 0; p < 4; p++) {
            int mm = p*32 + ldm;
            As[mm*ASTR + ldk+0] = ra[p].x;
            As[mm*ASTR + ldk+1] = ra[p].y;
            As[mm*ASTR + ldk+2] = ra[p].z;
            As[mm*ASTR + ldk+3] = ra[p].w;
        }
        Bs[(kqB+0)*64 + dB] = rb0.x;
        Bs[(kqB+1)*64 + dB] = rb0.y;
        Bs[(kqB+2)*64 + dB] = rb0.z;
        Bs[(kqB+3)*64 + dB] = rb0.w;
        Bs[(kqB+4)*64 + dB] = rb1.x;
        Bs[(kqB+5)*64 + dB] = rb1.y;
        Bs[(kqB+6)*64 + dB] = rb1.z;
        Bs[(kqB+7)*64 + dB] = rb1.w;
        __syncthreads();

        // prefetch next tile (LDG latency hidden by compute below)
        if (it + 1 < KITER) {
            int kb = kb0 + (it+1)*KT4;
            #pragma unroll
            for (int p = 0; p < 4; p++)
                ra[p] = *(const float4*)&g_crop[(size_t)(mbase + p*32 + ldm)*FAN + kb + ldk];
            rb0 = *(const float4*)&wenc[(size_t)dB*FAN + kb + kqB];
            rb1 = *(const float4*)&wenc[(size_t)dB*FAN + kb + kqB + 4];
        }

        #pragma unroll 8
        for (int kk = 0; kk < KT4; kk++) {
            float a0 = As[(m0+0)*ASTR + kk];
            float a1 = As[(m0+1)*ASTR + kk];
            float a2 = As[(m0+2)*ASTR + kk];
            float a3 = As[(m0+3)*ASTR + kk];
            float4 b0 = *(const float4*)&Bs[kk*64 + n0];
            float4 b1 = *(const float4*)&Bs[kk*64 + n0 + 4];
            acc[0][0] += a0*b0.x; acc[0][1] += a0*b0.y; acc[0][2] += a0*b0.z; acc[0][3] += a0*b0.w;
            acc[0][4] += a0*b1.x; acc[0][5] += a0*b1.y; acc[0][6] += a0*b1.z; acc[0][7] += a0*b1.w;
            acc[1][0] += a1*b0.x; acc[1][1] += a1*b0.y; acc[1][2] += a1*b0.z; acc[1][3] += a1*b0.w;
            acc[1][4] += a1*b1.x; acc[1][5] += a1*b1.y; acc[1][6] += a1*b1.z; acc[1][7] += a1*b1.w;
            acc[2][0] += a2*b0.x; acc[2][1] += a2*b0.y; acc[2][2] += a2*b0.z; acc[2][3] += a2*b0.w;
            acc[2][4] += a2*b1.x; acc[2][5] += a2*b1.y; acc[2][6] += a2*b1.z; acc[2][7] += a2*b1.w;
            acc[3][0] += a3*b0.x; acc[3][1] += a3*b0.y; acc[3][2] += a3*b0.z; acc[3][3] += a3*b0.w;
            acc[3][4] += a3*b1.x; acc[3][5] += a3*b1.y; acc[3][6] += a3*b1.z; acc[3][7] += a3*b1.w;
        }
        __syncthreads();
    }

    // write coalesced partials (no atomics)
    size_t pbase = ((size_t)blockIdx.y*MTOT + mbase + m0)*64 + n0;
    #pragma unroll
    for (int i = 0; i < 4; i++) {
        float4 w0 = make_float4(acc[i][0], acc[i][1], acc[i][2], acc[i][3]);
        float4 w1 = make_float4(acc[i][4], acc[i][5], acc[i][6], acc[i][7]);
        *(float4*)&g_encp[pbase + (size_t)i*64]     = w0;
        *(float4*)&g_encp[pbase + (size_t)i*64 + 4] = w1;
    }
}

// ================= K5: reduce partials + zi sample/kl + dec GEMM + small*c_few ============
__global__ void k5_zi_dec(const float* __restrict__ epszi,
                          const float* __restrict__ wdec,   // (1568, 32)
                          const float* __restrict__ bdec,
                          const float* __restrict__ benc,
                          float* __restrict__ out)
{
    int m = blockIdx.x, t = threadIdx.x;
    __shared__ float zsh[ZID];
    __shared__ float ench[64];
    if (t < 64) {
        float s = benc[t];
        #pragma unroll 7
        for (int sp = 0; sp < NSPLIT; sp++)
            s += g_encp[((size_t)sp*MTOT + m)*64 + t];
        ench[t] = s;
    }
    __syncthreads();
    if (t < ZID) {
        float mu = ench[t];
        float sp = ench[32 + t];
        float sd = softplusf_(sp) + 1e-4f;
        float s  = mu + sd * epszi[m*ZID + t];
        float kl = 0.5f*(mu*mu + sd*sd) - logf(sd) - 0.5f;
        out[OFF_ZIS + m*ZID + t] = s;
        out[OFF_ZIK + m*ZID + t] = kl;
        zsh[t] = s;
    }
    __syncthreads();
    float cf = g_cf[m];
    for (int f = t; f < SMALLF; f += 256) {
        const float4* wr = (const float4*)(wdec + (size_t)f*ZID);
        float acc = bdec[f];
        #pragma unroll
        for (int q = 0; q < 8; q++) {
            float4 w4 = wr[q];
            acc += w4.x*zsh[q*4+0] + w4.y*zsh[q*4+1]
                 + w4.z*zsh[q*4+2] + w4.w*zsh[q*4+3];
        }
        float r = (f < 784) ? softplusf_(acc) : sigmoidf_(acc);
        g_smallw[m*SMALLF + f] = r * cf;
    }
}

// ================= K6: uncrop -> big_img (out), big_mask_non (out), big_weight (scratch) ====
__global__ void k6_uncrop(float* __restrict__ out)
{
    int m = blockIdx.x, t = threadIdx.x;
    __shared__ float sm[SMALLF];
    __shared__ float xs[WRAW], ys[WRAW];
    for (int i = t; i < SMALLF; i += 256) sm[i] = g_smallw[m*SMALLF + i];
    if (t < WRAW) {
        float bx = g_bxf[m], bw = g_bwf[m];
        float by = g_byf[m], bh = g_bhf[m];
        xs[t] = ((float)t + 0.5f - (bx - 0.5f*bw)) / bw * (float)CROPSZ - 0.5f;
        ys[t] = ((float)t + 0.5f - (by - 0.5f*bh)) / bh * (float)CROPSZ - 0.5f;
    }
    __syncthreads();
    size_t base = (size_t)m * PIX;
    for (int p = t; p < PIX; p += 256) {
        int X = p >> 7, Y = p & 127;
        float x = xs[X], y = ys[Y];
        float w = 0.0f, im = 0.0f;
        if (x > -1.0f && x < (float)CROPSZ && y > -1.0f && y < (float)CROPSZ) {
            float x0f = floorf(x), y0f = floorf(y);
            int x0 = (int)x0f, y0 = (int)y0f;
            float wx1 = x - x0f, wy1 = y - y0f;
            float wx0 = 1.0f - wx1, wy0 = 1.0f - wy1;
            bool xa = (x0   >= 0 && x0   < CROPSZ);
            bool xb = (x0+1 >= 0 && x0+1 < CROPSZ);
            bool ya = (y0   >= 0 && y0   < CROPSZ);
            bool yb = (y0+1 >= 0 && y0+1 < CROPSZ);
            float w00 = wx0*wy0, w10 = wx1*wy0, w01 = wx0*wy1, w11 = wx1*wy1;
            int i00 = x0*CROPSZ + y0;
            #pragma unroll
            for (int ch = 0; ch < 2; ch++) {
                const float* img = sm + ch*784;
                float v00 = (xa&&ya) ? img[i00]          : 0.0f;
                float v10 = (xb&&ya) ? img[i00+CROPSZ]   : 0.0f;
                float v01 = (xa&&yb) ? img[i00+1]        : 0.0f;
                float v11 = (xb&&yb) ? img[i00+CROPSZ+1] : 0.0f;
                float v = v00*w00 + v10*w10 + v01*w01 + v11*w11;
                if (ch == 0) w = v; else im = v;
            }
        }
        g_bigw[base + p] = w;
        out[OFF_BMNON + base + p] = tanhf(w);
        out[OFF_BIMG  + base + p] = im;
    }
}

// ================= K7: sum over k -> big_mask =================
__global__ void k7_mask(float* __restrict__ out)
{
    int g = blockIdx.x*256 + threadIdx.x;   // < 8*16384
    int b = g >> 14, p = g & 16383;
    float v[KOBJ];
    float s = 0.0f;
    #pragma unroll
    for (int kk = 0; kk < KOBJ; kk++) {
        v[kk] = g_bigw[(size_t)(kk*BATCH+b)*PIX + p];
        s += v[kk];
    }
    float ts = tanhf(s);
    float inv = 1.0f / fmaxf(s, 1e-6f);
    #pragma unroll
    for (int kk = 0; kk < KOBJ; kk++)
        out[OFF_BMASK + (size_t)(kk*BATCH+b)*PIX + p] = ts * (v[kk] * inv);
}

// ================= launcher =================
extern "C" void kernel_launch(void* const* d_in, const int* in_sizes, int n_in,
                              void* d_out, int out_size)
{
    const float* logit = (const float*)d_in[0];
    const float* zmu   = (const float*)d_in[1];
    const float* zstd  = (const float*)d_in[2];
    const float* zeps  = (const float*)d_in[3];
    const float* epszi = (const float*)d_in[4];
    const float* feat  = (const float*)d_in[5];
    const float* wz    = (const float*)d_in[6];
    const float* bz    = (const float*)d_in[7];
    const float* wenc  = (const float*)d_in[8];
    const float* benc  = (const float*)d_in[9];
    const float* wdec  = (const float*)d_in[10];
    const float* bdec  = (const float*)d_in[11];
    float* out = (float*)d_out;

    k1_site<<<32, 256>>>(logit, zmu, zstd, zeps, wz, bz, out);
    k2_topk<<<BATCH, 1024>>>(out);
    k3_crop<<<MTOT, 256>>>(feat);
    dim3 g4(3, NSPLIT);
    k4_gemm<<<g4, 256>>>(wenc);
    k5_zi_dec<<<MTOT, 256>>>(epszi, wdec, bdec, benc, out);
    k6_uncrop<<<MTOT, 256>>>(out);
    k7_mask<<<(BATCH*PIX)/256, 256>>>(out);
}